// round 3
// baseline (speedup 1.0000x reference)
#include <cuda_runtime.h>
#include <stdint.h>

#define NUM_OBJ_CLS 151
#define NUM_REL_CLS 51

// ---------------------------------------------------------------------------
// obj_dists = exact one-hot (softmax of +/-1000 fp32 logits: exp(-2000)
// underflows to 0). Single kernel: each thread emits one float4 of the
// [n_obj, 151] block, computing row/col per element (div-by-151 -> mulhi).
// ---------------------------------------------------------------------------
__global__ void onehot_kernel(const int* __restrict__ labels,
                              float* __restrict__ out,
                              int n_floats) {
    int i = blockIdx.x * blockDim.x + threadIdx.x;
    int f0 = i * 4;
    if (f0 >= n_floats) return;

    if (f0 + 3 < n_floats) {
        float4 v;
        {
            int r = f0 / NUM_OBJ_CLS, c = f0 - r * NUM_OBJ_CLS;
            v.x = (__ldg(&labels[r]) == c) ? 1.0f : 0.0f;
        }
        {
            int f = f0 + 1;
            int r = f / NUM_OBJ_CLS, c = f - r * NUM_OBJ_CLS;
            v.y = (__ldg(&labels[r]) == c) ? 1.0f : 0.0f;
        }
        {
            int f = f0 + 2;
            int r = f / NUM_OBJ_CLS, c = f - r * NUM_OBJ_CLS;
            v.z = (__ldg(&labels[r]) == c) ? 1.0f : 0.0f;
        }
        {
            int f = f0 + 3;
            int r = f / NUM_OBJ_CLS, c = f - r * NUM_OBJ_CLS;
            v.w = (__ldg(&labels[r]) == c) ? 1.0f : 0.0f;
        }
        *(float4*)(out + f0) = v;
    } else {
        for (int f = f0; f < n_floats; f++) {
            int r = f / NUM_OBJ_CLS, c = f - r * NUM_OBJ_CLS;
            out[f] = (__ldg(&labels[r]) == c) ? 1.0f : 0.0f;
        }
    }
}

// ---------------------------------------------------------------------------
// rel_dists: warp handles 32 pairs/chunk.
//  Phase A: 32 independent pair->label->base chains, one per lane (MLP x32).
//  Phase B: gather 32 rows (51 floats each) from L2-resident table into smem.
//  Phase C: emit the chunk (exactly 408 float4, 128B-aligned: 32*204 = 6528
//           = 51*128) as dense coalesced streaming stores.
// ---------------------------------------------------------------------------
#define WARPS_PER_BLOCK 4
#define CHUNK_FLOATS (32 * NUM_REL_CLS)   // 1632
#define CHUNK_VEC4   (CHUNK_FLOATS / 4)   // 408

__global__ void rel_gather_kernel(const int* __restrict__ labels,
                                  const int2* __restrict__ pairs,
                                  const float* __restrict__ table,
                                  float* __restrict__ out,
                                  int n_pairs) {
    __shared__ float buf[WARPS_PER_BLOCK][CHUNK_FLOATS];

    const int lane   = threadIdx.x & 31;
    const int wlocal = threadIdx.x >> 5;
    const int warp_id   = (blockIdx.x * blockDim.x + threadIdx.x) >> 5;
    const int num_warps = (gridDim.x * blockDim.x) >> 5;
    float* __restrict__ sbuf = buf[wlocal];

    const int n_chunks = (n_pairs + 31) >> 5;

    for (int chunk = warp_id; chunk < n_chunks; chunk += num_warps) {
        const int p0 = chunk << 5;
        // Phase A: per-lane index resolution.
        int base = 0;
        if (p0 + lane < n_pairs) {
            int2 pr = __ldg(&pairs[p0 + lane]);
            int h = __ldg(&labels[pr.x]);
            int t = __ldg(&labels[pr.y]);
            base = (h * NUM_OBJ_CLS + t) * NUM_REL_CLS;
        }

        const int cnt = min(32, n_pairs - p0);
        if (cnt == 32) {
            // Phase B: rows -> smem.
            #pragma unroll 4
            for (int j = 0; j < 32; j++) {
                int b = __shfl_sync(0xffffffffu, base, j);
                sbuf[j * NUM_REL_CLS + lane] = __ldg(table + b + lane);
                if (lane < (NUM_REL_CLS - 32))
                    sbuf[j * NUM_REL_CLS + 32 + lane] = __ldg(table + b + 32 + lane);
            }
            __syncwarp();

            // Phase C: dense float4 streaming stores (chunk base 128B-aligned).
            const float4* __restrict__ s4 = (const float4*)sbuf;
            float4* __restrict__ d4 = (float4*)(out + (size_t)p0 * NUM_REL_CLS);
            #pragma unroll
            for (int it = 0; it < 13; it++) {
                int f = it * 32 + lane;
                if (f < CHUNK_VEC4) __stcs(&d4[f], s4[f]);
            }
            __syncwarp();
        } else {
            // Tail chunk (rare / absent when n_pairs % 32 == 0).
            for (int j = 0; j < cnt; j++) {
                int b = __shfl_sync(0xffffffffu, base, j);
                float* __restrict__ dst = out + (size_t)(p0 + j) * NUM_REL_CLS;
                dst[lane] = __ldg(table + b + lane);
                if (lane < (NUM_REL_CLS - 32))
                    dst[32 + lane] = __ldg(table + b + 32 + lane);
            }
        }
    }
}

extern "C" void kernel_launch(void* const* d_in, const int* in_sizes, int n_in,
                              void* d_out, int out_size) {
    const int*   labels = (const int*)d_in[0];          // [N_OBJ] int32
    const int2*  pairs  = (const int2*)d_in[1];         // [N_PAIRS, 2] int32
    const float* table  = (const float*)d_in[2];        // [151,151,51] f32

    const int n_obj   = in_sizes[0];
    const int n_pairs = in_sizes[1] / 2;

    float* obj_out = (float*)d_out;                               // [n_obj, 151]
    float* rel_out = obj_out + (size_t)n_obj * NUM_OBJ_CLS;       // [n_pairs, 51]

    // obj_dists: single fused one-hot kernel, one float4 per thread.
    int n_obj_floats = n_obj * NUM_OBJ_CLS;
    int n_vec = (n_obj_floats + 3) / 4;
    onehot_kernel<<<(n_vec + 255) / 256, 256>>>(labels, obj_out, n_obj_floats);

    // rel_dists: 148 SMs x 8 resident blocks (128 thr, 26KB smem) = single wave.
    rel_gather_kernel<<<1184, 32 * WARPS_PER_BLOCK>>>(labels, pairs, table,
                                                      rel_out, n_pairs);
}

// round 4
// speedup vs baseline: 1.0971x; 1.0971x over previous
#include <cuda_runtime.h>
#include <stdint.h>

#define NUM_OBJ_CLS 151
#define NUM_REL_CLS 51
#define CHUNK_VEC4  ((32 * NUM_REL_CLS) / 4)   // 408 float4 per 32-pair chunk

// ---------------------------------------------------------------------------
// obj_dists = exact one-hot (softmax of +/-1000 fp32 logits underflows).
// One float4 of the [n_obj, 151] block per thread.
// ---------------------------------------------------------------------------
__global__ void onehot_kernel(const int* __restrict__ labels,
                              float* __restrict__ out,
                              int n_floats) {
    int i = blockIdx.x * blockDim.x + threadIdx.x;
    int f0 = i * 4;
    if (f0 >= n_floats) return;

    if (f0 + 3 < n_floats) {
        float4 v;
        #pragma unroll
        for (int k = 0; k < 4; k++) {
            int f = f0 + k;
            int r = f / NUM_OBJ_CLS, c = f - r * NUM_OBJ_CLS;
            float val = (__ldg(&labels[r]) == c) ? 1.0f : 0.0f;
            if (k == 0) v.x = val; else if (k == 1) v.y = val;
            else if (k == 2) v.z = val; else v.w = val;
        }
        *(float4*)(out + f0) = v;
    } else {
        for (int f = f0; f < n_floats; f++) {
            int r = f / NUM_OBJ_CLS, c = f - r * NUM_OBJ_CLS;
            out[f] = (__ldg(&labels[r]) == c) ? 1.0f : 0.0f;
        }
    }
}

// ---------------------------------------------------------------------------
// rel_dists: warp handles 32 pairs. Per-lane index resolution (MLP x32),
// then each lane assembles dense float4 outputs directly in registers:
//   vec index v -> floats 4v..4v+3, straddling rows j0=(4v)/51, j3=(4v+3)/51.
// Row bases fetched by shfl; 4 scalar table loads (L2-hot, near-contiguous
// across lanes); one aligned STG.128 per float4. No smem, no syncs.
// 408 = 12*32 + 24: 12 full warp-iterations + one 24-lane tail iteration.
// ---------------------------------------------------------------------------
__global__ void __launch_bounds__(256)
rel_gather_kernel(const int* __restrict__ labels,
                  const int2* __restrict__ pairs,
                  const float* __restrict__ table,
                  float* __restrict__ out,
                  int n_pairs) {
    const int lane = threadIdx.x & 31;
    const int warp_id   = (blockIdx.x * blockDim.x + threadIdx.x) >> 5;
    const int num_warps = (gridDim.x * blockDim.x) >> 5;
    const int n_chunks = n_pairs >> 5;   // full 32-pair chunks

    for (int chunk = warp_id; chunk < n_chunks; chunk += num_warps) {
        const int p0 = chunk << 5;

        // Phase A: 32 independent pair->label->base chains, one per lane.
        int2 pr = __ldg(&pairs[p0 + lane]);
        int h = __ldg(&labels[pr.x]);
        int t = __ldg(&labels[pr.y]);
        int base = (h * NUM_OBJ_CLS + t) * NUM_REL_CLS;

        float4* __restrict__ d4 = (float4*)(out + (size_t)p0 * NUM_REL_CLS);

        // Phase B: 12 full iterations, all 32 lanes produce one float4 each.
        #pragma unroll 4
        for (int it = 0; it < 12; it++) {
            int v  = it * 32 + lane;          // vec4 index within chunk (<384)
            int f0 = v * 4;                   // first float index (<1536)
            int j0 = f0 / NUM_REL_CLS;        // first source row (<=30)
            int c0 = f0 - j0 * NUM_REL_CLS;
            int j3 = (f0 + 3) / NUM_REL_CLS;  // last source row
            int b0 = __shfl_sync(0xffffffffu, base, j0);
            int b1 = __shfl_sync(0xffffffffu, base, j3);

            float4 vv;
            vv.x = __ldg(table + b0 + c0);
            vv.y = (c0 + 1 < NUM_REL_CLS) ? __ldg(table + b0 + c0 + 1)
                                          : __ldg(table + b1 + c0 + 1 - NUM_REL_CLS);
            vv.z = (c0 + 2 < NUM_REL_CLS) ? __ldg(table + b0 + c0 + 2)
                                          : __ldg(table + b1 + c0 + 2 - NUM_REL_CLS);
            vv.w = (c0 + 3 < NUM_REL_CLS) ? __ldg(table + b0 + c0 + 3)
                                          : __ldg(table + b1 + c0 + 3 - NUM_REL_CLS);
            __stcs(&d4[v], vv);
        }

        // Tail iteration: v = 384 + lane, active for lane < 24 (408 total).
        {
            int v  = 384 + lane;
            int f0 = v * 4;
            int j0 = min(f0 / NUM_REL_CLS, 31);
            int c0 = f0 - (f0 / NUM_REL_CLS) * NUM_REL_CLS;
            int j3 = min((f0 + 3) / NUM_REL_CLS, 31);
            int b0 = __shfl_sync(0xffffffffu, base, j0);
            int b1 = __shfl_sync(0xffffffffu, base, j3);
            if (v < CHUNK_VEC4) {
                float4 vv;
                vv.x = __ldg(table + b0 + c0);
                vv.y = (c0 + 1 < NUM_REL_CLS) ? __ldg(table + b0 + c0 + 1)
                                              : __ldg(table + b1 + c0 + 1 - NUM_REL_CLS);
                vv.z = (c0 + 2 < NUM_REL_CLS) ? __ldg(table + b0 + c0 + 2)
                                              : __ldg(table + b1 + c0 + 2 - NUM_REL_CLS);
                vv.w = (c0 + 3 < NUM_REL_CLS) ? __ldg(table + b0 + c0 + 3)
                                              : __ldg(table + b1 + c0 + 3 - NUM_REL_CLS);
                __stcs(&d4[v], vv);
            }
        }
    }

    // Leftover pairs (n_pairs % 32): rare; handled scalar by warp 0.
    if (warp_id == 0) {
        for (int p = n_chunks << 5; p < n_pairs; p++) {
            int2 pr = __ldg(&pairs[p]);
            int h = __ldg(&labels[pr.x]);
            int t = __ldg(&labels[pr.y]);
            int b = (h * NUM_OBJ_CLS + t) * NUM_REL_CLS;
            float* __restrict__ dst = out + (size_t)p * NUM_REL_CLS;
            if (lane < NUM_REL_CLS) dst[lane] = __ldg(table + b + lane);
            if (lane < NUM_REL_CLS - 32) dst[32 + lane] = __ldg(table + b + 32 + lane);
        }
    }
}

extern "C" void kernel_launch(void* const* d_in, const int* in_sizes, int n_in,
                              void* d_out, int out_size) {
    const int*   labels = (const int*)d_in[0];          // [N_OBJ] int32
    const int2*  pairs  = (const int2*)d_in[1];         // [N_PAIRS, 2] int32
    const float* table  = (const float*)d_in[2];        // [151,151,51] f32

    const int n_obj   = in_sizes[0];
    const int n_pairs = in_sizes[1] / 2;

    float* obj_out = (float*)d_out;                               // [n_obj, 151]
    float* rel_out = obj_out + (size_t)n_obj * NUM_OBJ_CLS;       // [n_pairs, 51]

    // obj_dists
    int n_obj_floats = n_obj * NUM_OBJ_CLS;
    int n_vec = (n_obj_floats + 3) / 4;
    onehot_kernel<<<(n_vec + 255) / 256, 256>>>(labels, obj_out, n_obj_floats);

    // rel_dists: 2048 blocks x 256 thr = 16384 warps, ~3.8 chunks each.
    rel_gather_kernel<<<2048, 256>>>(labels, pairs, table, rel_out, n_pairs);
}

// round 5
// speedup vs baseline: 1.1787x; 1.0743x over previous
#include <cuda_runtime.h>
#include <stdint.h>

#define NUM_OBJ_CLS 151
#define NUM_REL_CLS 51
#define CHUNK_FLOATS (32 * NUM_REL_CLS)        // 1632 floats per 32-pair chunk
#define WARPS_PER_BLOCK 8

// ---------------------------------------------------------------------------
// obj_dists = exact one-hot (softmax of +/-1000 fp32 logits underflows).
// One float4 of the [n_obj, 151] block per thread.
// ---------------------------------------------------------------------------
__global__ void onehot_kernel(const int* __restrict__ labels,
                              float* __restrict__ out,
                              int n_floats) {
    int i = blockIdx.x * blockDim.x + threadIdx.x;
    int f0 = i * 4;
    if (f0 >= n_floats) return;

    if (f0 + 3 < n_floats) {
        float4 v;
        #pragma unroll
        for (int k = 0; k < 4; k++) {
            int f = f0 + k;
            int r = f / NUM_OBJ_CLS, c = f - r * NUM_OBJ_CLS;
            float val = (__ldg(&labels[r]) == c) ? 1.0f : 0.0f;
            if (k == 0) v.x = val; else if (k == 1) v.y = val;
            else if (k == 2) v.z = val; else v.w = val;
        }
        *(float4*)(out + f0) = v;
    } else {
        for (int f = f0; f < n_floats; f++) {
            int r = f / NUM_OBJ_CLS, c = f - r * NUM_OBJ_CLS;
            out[f] = (__ldg(&labels[r]) == c) ? 1.0f : 0.0f;
        }
    }
}

// ---------------------------------------------------------------------------
// rel_dists: warp handles 32 pairs (one chunk = 1632 floats = 6528 B,
// 128B-aligned since p0 % 32 == 0).
//  Phase A: 32 independent pair->label->base chains, one per lane.
//  Per 128-float slice: 4 stride-1 LDG.32 (each covers 128 contiguous
//  chunk bytes; row bases via shfl) -> 512B smem buffer (stride-1 STS,
//  conflict-free) -> syncwarp -> LDS.128 -> dense aligned STG.128 (__stcs).
//  Double-buffered, one syncwarp per slice.
// ---------------------------------------------------------------------------
__global__ void __launch_bounds__(32 * WARPS_PER_BLOCK)
rel_gather_kernel(const int* __restrict__ labels,
                  const int2* __restrict__ pairs,
                  const float* __restrict__ table,
                  float* __restrict__ out,
                  int n_pairs) {
    __shared__ float xbuf[WARPS_PER_BLOCK][2][128];

    const int lane   = threadIdx.x & 31;
    const int wlocal = threadIdx.x >> 5;
    const int warp_id   = (blockIdx.x * blockDim.x + threadIdx.x) >> 5;
    const int num_warps = (gridDim.x * blockDim.x) >> 5;
    const int n_chunks  = n_pairs >> 5;

    for (int chunk = warp_id; chunk < n_chunks; chunk += num_warps) {
        const int p0 = chunk << 5;

        // Phase A: per-lane index resolution (MLP x32).
        int2 pr = __ldg(&pairs[p0 + lane]);
        int h = __ldg(&labels[pr.x]);
        int t = __ldg(&labels[pr.y]);
        int base = (h * NUM_OBJ_CLS + t) * NUM_REL_CLS;

        float4* __restrict__ d4 = (float4*)(out + (size_t)p0 * NUM_REL_CLS);

        // 12 full 128-float slices.
        #pragma unroll 2
        for (int it = 0; it < 12; it++) {
            float* __restrict__ sb = xbuf[wlocal][it & 1];
            const int fbase = it * 128;
            #pragma unroll
            for (int k = 0; k < 4; k++) {
                int f = fbase + 32 * k + lane;       // contiguous across lanes
                int j = f / NUM_REL_CLS;             // source pair row (0..31)
                int c = f - j * NUM_REL_CLS;
                int b = __shfl_sync(0xffffffffu, base, j);
                sb[32 * k + lane] = __ldg(table + b + c);
            }
            __syncwarp();
            float4 vv = *(const float4*)(sb + 4 * lane);
            __stcs(&d4[it * 32 + lane], vv);
        }

        // Tail slice: floats 1536..1631 (96 floats = 24 float4).
        {
            float* __restrict__ sb = xbuf[wlocal][0];
            __syncwarp();                            // protect buffer reuse
            #pragma unroll
            for (int k = 0; k < 3; k++) {
                int f = 1536 + 32 * k + lane;        // max 1631 < 1632
                int j = f / NUM_REL_CLS;
                int c = f - j * NUM_REL_CLS;
                int b = __shfl_sync(0xffffffffu, base, j);
                sb[32 * k + lane] = __ldg(table + b + c);
            }
            __syncwarp();
            if (lane < 24) {
                float4 vv = *(const float4*)(sb + 4 * lane);
                __stcs(&d4[384 + lane], vv);
            }
            __syncwarp();                            // before next chunk reuses buf 0
        }
    }

    // Leftover pairs (n_pairs % 32): absent for 2M pairs, kept for generality.
    if (warp_id == 0) {
        for (int p = n_chunks << 5; p < n_pairs; p++) {
            int2 pr = __ldg(&pairs[p]);
            int h = __ldg(&labels[pr.x]);
            int t = __ldg(&labels[pr.y]);
            int b = (h * NUM_OBJ_CLS + t) * NUM_REL_CLS;
            float* __restrict__ dst = out + (size_t)p * NUM_REL_CLS;
            if (lane < NUM_REL_CLS) dst[lane] = __ldg(table + b + lane);
            if (lane < NUM_REL_CLS - 32) dst[32 + lane] = __ldg(table + b + 32 + lane);
        }
    }
}

extern "C" void kernel_launch(void* const* d_in, const int* in_sizes, int n_in,
                              void* d_out, int out_size) {
    const int*   labels = (const int*)d_in[0];          // [N_OBJ] int32
    const int2*  pairs  = (const int2*)d_in[1];         // [N_PAIRS, 2] int32
    const float* table  = (const float*)d_in[2];        // [151,151,51] f32

    const int n_obj   = in_sizes[0];
    const int n_pairs = in_sizes[1] / 2;

    float* obj_out = (float*)d_out;                               // [n_obj, 151]
    float* rel_out = obj_out + (size_t)n_obj * NUM_OBJ_CLS;       // [n_pairs, 51]

    // obj_dists
    int n_obj_floats = n_obj * NUM_OBJ_CLS;
    int n_vec = (n_obj_floats + 3) / 4;
    onehot_kernel<<<(n_vec + 255) / 256, 256>>>(labels, obj_out, n_obj_floats);

    // rel_dists: 2048 blocks x 256 thr = 16384 warps, ~3.8 chunks each.
    rel_gather_kernel<<<2048, 32 * WARPS_PER_BLOCK>>>(labels, pairs, table,
                                                      rel_out, n_pairs);
}